// round 1
// baseline (speedup 1.0000x reference)
#include <cuda_runtime.h>

// Problem constants
#define Bb    8
#define Nseq  4096
#define DIMc  1024
#define Hh    16
#define Dd    64
#define Mm    (Bb * Nseq)      // 32768 rows
#define NSPLIT 32              // sequence splits for column reductions

// ---------------- scratch (static device allocations only) ----------------
__device__ float g_w[Mm * DIMc];                 // 128 MB: qkv output w, layout (b, n, h*d)
__device__ float g_Pi[Mm * Hh];                  // 2 MB: softmax over heads, (b, n, h)
__device__ float g_part1[NSPLIT * Bb * DIMc];    // partial column sums of w^2
__device__ float g_part2[NSPLIT * Bb * DIMc];    // partial weighted column sums
__device__ float g_innorm[Bb * DIMc];            // 1 / max(sum_n w^2, eps^2)
__device__ float g_Sp[(Mm / 8) * Hh];            // per-block partial sums of Pi over n
__device__ float g_invS[Bb * Hh];                // 1 / (sum_n Pi + 1e-8)
__device__ float g_attn[Bb * DIMc];              // 1 / (1 + dots), indexed [b][h*64+d]

// ---------------- GEMM 1: w = x @ Wqkv^T  (both operands K-major) ----------
// C[m][n] = sum_k A[m][k] * W[n][k];  M=32768, N=1024, K=1024
__global__ __launch_bounds__(256, 2)
void gemm_xw(const float* __restrict__ A, const float* __restrict__ W) {
    const int K = DIMc, NN = DIMc;
    __shared__ float As[8][128];
    __shared__ float Bs[8][128];
    int tid = threadIdx.x;
    int bn = blockIdx.x, bm = blockIdx.y;
    int tx = tid & 15, ty = tid >> 4;
    int lrow = tid >> 1, lcol = (tid & 1) << 2;

    const float* Ap = A + (size_t)(bm * 128 + lrow) * K + lcol;
    const float* Wp = W + (size_t)(bn * 128 + lrow) * K + lcol;
    float4 a4 = *(const float4*)Ap;
    float4 b4 = *(const float4*)Wp;

    float acc[8][8] = {};
    const int nT = K / 8;
    for (int t = 0; t < nT; ++t) {
        As[lcol + 0][lrow] = a4.x; As[lcol + 1][lrow] = a4.y;
        As[lcol + 2][lrow] = a4.z; As[lcol + 3][lrow] = a4.w;
        Bs[lcol + 0][lrow] = b4.x; Bs[lcol + 1][lrow] = b4.y;
        Bs[lcol + 2][lrow] = b4.z; Bs[lcol + 3][lrow] = b4.w;
        __syncthreads();
        if (t + 1 < nT) {
            a4 = *(const float4*)(Ap + (t + 1) * 8);
            b4 = *(const float4*)(Wp + (t + 1) * 8);
        }
#pragma unroll
        for (int kk = 0; kk < 8; ++kk) {
            float ra[8], rb[8];
#pragma unroll
            for (int i = 0; i < 8; i++) ra[i] = As[kk][ty * 8 + i];
#pragma unroll
            for (int j = 0; j < 8; j++) rb[j] = Bs[kk][tx * 8 + j];
#pragma unroll
            for (int i = 0; i < 8; i++)
#pragma unroll
                for (int j = 0; j < 8; j++)
                    acc[i][j] = fmaf(ra[i], rb[j], acc[i][j]);
        }
        __syncthreads();
    }
    float* Cp = g_w + (size_t)(bm * 128 + ty * 8) * NN + bn * 128 + tx * 8;
#pragma unroll
    for (int i = 0; i < 8; i++)
#pragma unroll
        for (int j = 0; j < 8; j++)
            Cp[(size_t)i * NN + j] = acc[i][j];
}

// ---------------- column sums of w^2 (partial, deterministic) --------------
__global__ void colsumsq_part() {
    int c  = blockIdx.x * 256 + threadIdx.x;   // 0..1023
    int sp = blockIdx.y;                       // split
    int b  = blockIdx.z;
    const int rows = Nseq / NSPLIT;            // 128
    const float* p = g_w + ((size_t)b * Nseq + (size_t)sp * rows) * DIMc + c;
    float acc = 0.f;
    for (int i = 0; i < rows; i++) {
        float v = p[(size_t)i * DIMc];
        acc = fmaf(v, v, acc);
    }
    g_part1[(sp * Bb + b) * DIMc + c] = acc;
}

__global__ void reduce_innorm() {
    int idx = blockIdx.x * 256 + threadIdx.x;  // 0..8191
    int b = idx >> 10, c = idx & 1023;
    float s = 0.f;
#pragma unroll
    for (int sp = 0; sp < NSPLIT; sp++) s += g_part1[(sp * Bb + b) * DIMc + c];
    // denom = max(sqrt(s), 1e-12)^2 = max(s, 1e-24)
    g_innorm[idx] = 1.0f / fmaxf(s, 1e-24f);
}

// ---------------- logits + softmax over heads + block-partial S ------------
// one warp per (b,n) row; 8 rows per block
__global__ void logits_softmax(const float* __restrict__ temp) {
    int warp = threadIdx.x >> 5, lane = threadIdx.x & 31;
    int r = blockIdx.x * 8 + warp;             // global row
    int b = r >> 12;
    const float* wrow = g_w + (size_t)r * DIMc;
    const float* inn  = g_innorm + b * DIMc;

    float acc[16];
#pragma unroll
    for (int h = 0; h < 16; h++) {
        int c = h * 64 + lane;
        float v0 = wrow[c];
        float v1 = wrow[c + 32];
        acc[h] = v0 * v0 * inn[c] + v1 * v1 * inn[c + 32];
    }
#pragma unroll
    for (int h = 0; h < 16; h++) {
        float s = acc[h];
#pragma unroll
        for (int o = 16; o; o >>= 1) s += __shfl_xor_sync(0xffffffffu, s, o);
        acc[h] = s * temp[h];
    }
    // softmax over the 16 heads (all lanes hold identical values)
    float mx = acc[0];
#pragma unroll
    for (int h = 1; h < 16; h++) mx = fmaxf(mx, acc[h]);
    float ssum = 0.f;
#pragma unroll
    for (int h = 0; h < 16; h++) { acc[h] = expf(acc[h] - mx); ssum += acc[h]; }
    float inv = 1.0f / ssum;
#pragma unroll
    for (int h = 0; h < 16; h++) acc[h] *= inv;

    __shared__ float sPi[8][16];
    if (lane == 0) {
#pragma unroll
        for (int h = 0; h < 16; h++) {
            g_Pi[(size_t)r * Hh + h] = acc[h];
            sPi[warp][h] = acc[h];
        }
    }
    __syncthreads();
    if (threadIdx.x < 16) {
        float s = 0.f;
#pragma unroll
        for (int w = 0; w < 8; w++) s += sPi[w][threadIdx.x];
        g_Sp[blockIdx.x * 16 + threadIdx.x] = s;
    }
}

// ---------------- reduce S over n -> invS ---------------------------------
__global__ void reduce_S() {
    int bh = blockIdx.x;                 // b*16 + h
    int b = bh >> 4, h = bh & 15;
    __shared__ float sm[128];
    float s = 0.f;
    const int blocksPerBatch = (Nseq / 8);   // 512 blocks of logits kernel per batch
    for (int i = threadIdx.x; i < blocksPerBatch; i += 128)
        s += g_Sp[(b * blocksPerBatch + i) * 16 + h];
    sm[threadIdx.x] = s;
    __syncthreads();
    for (int o = 64; o; o >>= 1) {
        if (threadIdx.x < o) sm[threadIdx.x] += sm[threadIdx.x + o];
        __syncthreads();
    }
    if (threadIdx.x == 0) g_invS[bh] = 1.0f / (sm[0] + 1e-8f);
}

// ---------------- weighted column sums: sum_n Pi * w^2 (partial) -----------
__global__ void dots_part() {
    int c  = blockIdx.x * 256 + threadIdx.x;
    int sp = blockIdx.y;
    int b  = blockIdx.z;
    int h  = c >> 6;                            // warp-uniform
    const int rows = Nseq / NSPLIT;
    const float* p   = g_w  + ((size_t)b * Nseq + (size_t)sp * rows) * DIMc + c;
    const float* pip = g_Pi + ((size_t)b * Nseq + (size_t)sp * rows) * Hh + h;
    float acc = 0.f;
    for (int i = 0; i < rows; i++) {
        float v = p[(size_t)i * DIMc];
        acc = fmaf(pip[i * Hh] * v, v, acc);
    }
    g_part2[(sp * Bb + b) * DIMc + c] = acc;
}

__global__ void reduce_attn() {
    int idx = blockIdx.x * 256 + threadIdx.x;  // 0..8191
    int b = idx >> 10, c = idx & 1023, h = c >> 6;
    float s = 0.f;
#pragma unroll
    for (int sp = 0; sp < NSPLIT; sp++) s += g_part2[(sp * Bb + b) * DIMc + c];
    float dots = s * g_invS[b * 16 + h];
    g_attn[idx] = 1.0f / (1.0f + dots);
}

// ---------------- GEMM 2: out = y @ Wout^T + bout,  y fused in A-load -----
// y[m][k] = -w[m][k] * Pi[m][k/64] * attn[b][k]
__global__ __launch_bounds__(256, 2)
void gemm_out(const float* __restrict__ W, const float* __restrict__ bias,
              float* __restrict__ C) {
    const int K = DIMc, NN = DIMc;
    __shared__ float As[8][128];
    __shared__ float Bs[8][128];
    int tid = threadIdx.x;
    int bn = blockIdx.x, bm = blockIdx.y;
    int tx = tid & 15, ty = tid >> 4;
    int lrow = tid >> 1, lcol = (tid & 1) << 2;

    int grow = bm * 128 + lrow;                // global m for A loads
    int bidx = grow >> 12;                     // batch
    const float* wbase  = g_w + (size_t)grow * K;
    const float* pibase = g_Pi + (size_t)grow * Hh;
    const float* atbase = g_attn + bidx * DIMc;
    const float* Wp = W + (size_t)(bn * 128 + lrow) * K + lcol;

    // A-load with fused elementwise transform
    auto loadA = [&](int t) -> float4 {
        int k = t * 8 + lcol;
        float4 wv = *(const float4*)(wbase + k);
        float pi  = pibase[k >> 6];            // float4 never crosses a head boundary
        float4 at = *(const float4*)(atbase + k);
        float4 r;
        r.x = -wv.x * pi * at.x;
        r.y = -wv.y * pi * at.y;
        r.z = -wv.z * pi * at.z;
        r.w = -wv.w * pi * at.w;
        return r;
    };

    float4 a4 = loadA(0);
    float4 b4 = *(const float4*)Wp;

    float acc[8][8] = {};
    const int nT = K / 8;
    for (int t = 0; t < nT; ++t) {
        As[lcol + 0][lrow] = a4.x; As[lcol + 1][lrow] = a4.y;
        As[lcol + 2][lrow] = a4.z; As[lcol + 3][lrow] = a4.w;
        Bs[lcol + 0][lrow] = b4.x; Bs[lcol + 1][lrow] = b4.y;
        Bs[lcol + 2][lrow] = b4.z; Bs[lcol + 3][lrow] = b4.w;
        __syncthreads();
        if (t + 1 < nT) {
            a4 = loadA(t + 1);
            b4 = *(const float4*)(Wp + (t + 1) * 8);
        }
#pragma unroll
        for (int kk = 0; kk < 8; ++kk) {
            float ra[8], rb[8];
#pragma unroll
            for (int i = 0; i < 8; i++) ra[i] = As[kk][ty * 8 + i];
#pragma unroll
            for (int j = 0; j < 8; j++) rb[j] = Bs[kk][tx * 8 + j];
#pragma unroll
            for (int i = 0; i < 8; i++)
#pragma unroll
                for (int j = 0; j < 8; j++)
                    acc[i][j] = fmaf(ra[i], rb[j], acc[i][j]);
        }
        __syncthreads();
    }
    int col0 = bn * 128 + tx * 8;
    float bv[8];
#pragma unroll
    for (int j = 0; j < 8; j++) bv[j] = bias[col0 + j];
    float* Cp = C + (size_t)(bm * 128 + ty * 8) * NN + col0;
#pragma unroll
    for (int i = 0; i < 8; i++)
#pragma unroll
        for (int j = 0; j < 8; j++)
            Cp[(size_t)i * NN + j] = acc[i][j] + bv[j];
}

// ---------------- launch ---------------------------------------------------
extern "C" void kernel_launch(void* const* d_in, const int* in_sizes, int n_in,
                              void* d_out, int out_size) {
    const float* x    = (const float*)d_in[0];   // (8, 4096, 1024)
    const float* Wqkv = (const float*)d_in[1];   // (1024, 1024)
    const float* temp = (const float*)d_in[2];   // (16, 1)
    const float* Wout = (const float*)d_in[3];   // (1024, 1024)
    const float* bout = (const float*)d_in[4];   // (1024,)
    float* out = (float*)d_out;

    dim3 gemmGrid(DIMc / 128, Mm / 128);         // (8, 256)
    gemm_xw<<<gemmGrid, 256>>>(x, Wqkv);
    colsumsq_part<<<dim3(DIMc / 256, NSPLIT, Bb), 256>>>();
    reduce_innorm<<<(Bb * DIMc) / 256, 256>>>();
    logits_softmax<<<Mm / 8, 256>>>(temp);
    reduce_S<<<Bb * Hh, 128>>>();
    dots_part<<<dim3(DIMc / 256, NSPLIT, Bb), 256>>>();
    reduce_attn<<<(Bb * DIMc) / 256, 256>>>();
    gemm_out<<<gemmGrid, 256>>>(Wout, bout, out);
}

// round 3
// speedup vs baseline: 2.8780x; 2.8780x over previous
#include <cuda_runtime.h>
#include <cstdint>

// Problem constants
#define Bb    8
#define Nseq  4096
#define DIMc  1024
#define Hh    16
#define Mm    (Bb * Nseq)      // 32768 rows
#define NSPLIT 32

// ---------------- scratch (static device allocations only) ----------------
__device__ float g_w [(size_t)Mm * DIMc];        // qkv output w, (b,n,h*d)
__device__ float g_y [(size_t)Mm * DIMc];        // transformed A for gemm2 (tf32-rounded)
__device__ float g_xr[(size_t)Mm * DIMc];        // x rounded to tf32
__device__ float g_W1r[DIMc * DIMc];             // Wqkv rounded to tf32
__device__ float g_W2r[DIMc * DIMc];             // Wout rounded to tf32
__device__ float g_Pi[Mm * Hh];
__device__ float g_part1[NSPLIT * Bb * DIMc];
__device__ float g_part2[NSPLIT * Bb * DIMc];
__device__ float g_innorm[Bb * DIMc];
__device__ float g_Sp[(Mm / 8) * Hh];
__device__ float g_invS[Bb * Hh];
__device__ float g_attn[Bb * DIMc];

// ============================ helpers ======================================
__device__ __forceinline__ float to_tf32(float x) {
    uint32_t u;
    asm("cvt.rna.tf32.f32 %0, %1;" : "=r"(u) : "f"(x));
    return __uint_as_float(u);
}
#define CP16(dst, src) \
    asm volatile("cp.async.cg.shared.global [%0], [%1], 16;" :: "r"(dst), "l"(src) : "memory")
#define CP_COMMIT() asm volatile("cp.async.commit_group;" ::: "memory")
#define CP_WAIT(n)  asm volatile("cp.async.wait_group %0;" :: "n"(n) : "memory")

__device__ __forceinline__ uint32_t smem_u32(const void* p) {
    uint32_t a;
    asm("{ .reg .u64 t; cvta.to.shared.u64 t, %1; cvt.u32.u64 %0, t; }"
        : "=r"(a) : "l"(p));
    return a;
}

__device__ __forceinline__ void mma_tf32(float c[4], uint32_t a0, uint32_t a1,
                                         uint32_t a2, uint32_t a3,
                                         uint32_t b0, uint32_t b1) {
    asm volatile(
        "mma.sync.aligned.m16n8k8.row.col.f32.tf32.tf32.f32 "
        "{%0,%1,%2,%3}, {%4,%5,%6,%7}, {%8,%9}, {%0,%1,%2,%3};"
        : "+f"(c[0]), "+f"(c[1]), "+f"(c[2]), "+f"(c[3])
        : "r"(a0), "r"(a1), "r"(a2), "r"(a3), "r"(b0), "r"(b1));
}

// ======================= tf32 GEMM (mma.sync) ==============================
// C[m][n] = sum_k A[m][k] * W[n][k] (+ bias[n])
// Block tile 128x128, 256 threads = 8 warps (2 M-warps x 4 N-warps),
// warp tile 64x32. K chunked by 16, 4-stage cp.async pipeline.
#define KC      16
#define SROW    20                        // padded smem row stride (floats)
#define STG_F   (128 * SROW * 2)          // floats per stage (A + B)
#define NSTG    4
#define GSMEM   (NSTG * STG_F * 4)        // bytes = 81920

__global__ __launch_bounds__(256)
void gemm_mma(const float* __restrict__ A, const float* __restrict__ W,
              float* __restrict__ C, const float* __restrict__ bias) {
    extern __shared__ float smem[];
    const int tid = threadIdx.x, wid = tid >> 5, lane = tid & 31;
    const int bn = blockIdx.x, bm = blockIdx.y;
    const int wm = wid & 1, wn = wid >> 1;        // 2 x 4 warp grid
    const int q  = lane >> 2, qc = lane & 3;      // fragment indices

    // cp.async assignments: 2 A segments + 2 B segments per thread per chunk
    const int sA0 = tid, sA1 = tid + 256;         // of 512 segs (128 rows x 4)
    const int rA0 = sA0 >> 2, cA0 = sA0 & 3;
    const int rA1 = sA1 >> 2, cA1 = sA1 & 3;
    const float* gA0 = A + (size_t)(bm * 128 + rA0) * DIMc + cA0 * 4;
    const float* gA1 = A + (size_t)(bm * 128 + rA1) * DIMc + cA1 * 4;
    const float* gB0 = W + (size_t)(bn * 128 + rA0) * DIMc + cA0 * 4;
    const float* gB1 = W + (size_t)(bn * 128 + rA1) * DIMc + cA1 * 4;
    const uint32_t smb = smem_u32(smem);
    const uint32_t oA0 = (rA0 * SROW + cA0 * 4) * 4;
    const uint32_t oA1 = (rA1 * SROW + cA1 * 4) * 4;
    const uint32_t oB0 = (128 * SROW + rA0 * SROW + cA0 * 4) * 4;
    const uint32_t oB1 = (128 * SROW + rA1 * SROW + cA1 * 4) * 4;

    auto load_chunk = [&](int c) {
        uint32_t st = smb + (uint32_t)((c & 3) * STG_F) * 4;
        const float* p0 = gA0 + c * KC;  CP16(st + oA0, p0);
        const float* p1 = gA1 + c * KC;  CP16(st + oA1, p1);
        const float* p2 = gB0 + c * KC;  CP16(st + oB0, p2);
        const float* p3 = gB1 + c * KC;  CP16(st + oB1, p3);
        CP_COMMIT();
    };

    float acc[4][4][4];
#pragma unroll
    for (int i = 0; i < 4; i++)
#pragma unroll
        for (int j = 0; j < 4; j++)
#pragma unroll
            for (int v = 0; v < 4; v++) acc[i][j][v] = 0.f;

    load_chunk(0); load_chunk(1); load_chunk(2);

    const int NCHUNK = DIMc / KC;        // 64
    for (int c = 0; c < NCHUNK; ++c) {
        CP_WAIT(2);
        __syncthreads();
        if (c + 3 < NCHUNK) load_chunk(c + 3);

        const float* As = smem + (c & 3) * STG_F;
        const float* Bs = As + 128 * SROW;
#pragma unroll
        for (int ks = 0; ks < 2; ++ks) {
            const int k0 = ks * 8;
            uint32_t af[4][4], bf[4][2];
#pragma unroll
            for (int i = 0; i < 4; i++) {
                int r0 = wm * 64 + i * 16 + q;
                af[i][0] = __float_as_uint(As[r0 * SROW + k0 + qc]);
                af[i][1] = __float_as_uint(As[(r0 + 8) * SROW + k0 + qc]);
                af[i][2] = __float_as_uint(As[r0 * SROW + k0 + qc + 4]);
                af[i][3] = __float_as_uint(As[(r0 + 8) * SROW + k0 + qc + 4]);
            }
#pragma unroll
            for (int j = 0; j < 4; j++) {
                int nr = wn * 32 + j * 8 + q;
                bf[j][0] = __float_as_uint(Bs[nr * SROW + k0 + qc]);
                bf[j][1] = __float_as_uint(Bs[nr * SROW + k0 + qc + 4]);
            }
#pragma unroll
            for (int i = 0; i < 4; i++)
#pragma unroll
                for (int j = 0; j < 4; j++)
                    mma_tf32(acc[i][j], af[i][0], af[i][1], af[i][2], af[i][3],
                             bf[j][0], bf[j][1]);
        }
        __syncthreads();
    }

    // epilogue
#pragma unroll
    for (int j = 0; j < 4; j++) {
        int col = bn * 128 + wn * 32 + j * 8 + qc * 2;
        float b0 = 0.f, b1 = 0.f;
        if (bias) { b0 = bias[col]; b1 = bias[col + 1]; }
#pragma unroll
        for (int i = 0; i < 4; i++) {
            int row = bm * 128 + wm * 64 + i * 16 + q;
            float2 v0 = make_float2(acc[i][j][0] + b0, acc[i][j][1] + b1);
            float2 v1 = make_float2(acc[i][j][2] + b0, acc[i][j][3] + b1);
            *(float2*)(C + (size_t)row * DIMc + col) = v0;
            *(float2*)(C + (size_t)(row + 8) * DIMc + col) = v1;
        }
    }
}

// =================== tf32 input rounding (RN, unbiased) ====================
__global__ void round_tf32_kernel(const float* __restrict__ src, float* __restrict__ dst) {
    size_t i = ((size_t)blockIdx.x * 256 + threadIdx.x) * 4;
    float4 v = *(const float4*)(src + i);
    v.x = to_tf32(v.x); v.y = to_tf32(v.y); v.z = to_tf32(v.z); v.w = to_tf32(v.w);
    *(float4*)(dst + i) = v;
}

// ---------------- column sums of w^2 (partial, deterministic) --------------
__global__ void colsumsq_part() {
    int c  = blockIdx.x * 256 + threadIdx.x;
    int sp = blockIdx.y;
    int b  = blockIdx.z;
    const int rows = Nseq / NSPLIT;
    const float* p = g_w + ((size_t)b * Nseq + (size_t)sp * rows) * DIMc + c;
    float acc = 0.f;
    for (int i = 0; i < rows; i++) {
        float v = p[(size_t)i * DIMc];
        acc = fmaf(v, v, acc);
    }
    g_part1[(sp * Bb + b) * DIMc + c] = acc;
}

__global__ void reduce_innorm() {
    int idx = blockIdx.x * 256 + threadIdx.x;
    int b = idx >> 10, c = idx & 1023;
    float s = 0.f;
#pragma unroll
    for (int sp = 0; sp < NSPLIT; sp++) s += g_part1[(sp * Bb + b) * DIMc + c];
    g_innorm[idx] = 1.0f / fmaxf(s, 1e-24f);
}

// ---------------- logits + softmax over heads ------------------------------
__global__ void logits_softmax(const float* __restrict__ temp) {
    int warp = threadIdx.x >> 5, lane = threadIdx.x & 31;
    int r = blockIdx.x * 8 + warp;
    int b = r >> 12;
    const float* wrow = g_w + (size_t)r * DIMc;
    const float* inn  = g_innorm + b * DIMc;

    float acc[16];
#pragma unroll
    for (int h = 0; h < 16; h++) {
        int c = h * 64 + lane;
        float v0 = wrow[c];
        float v1 = wrow[c + 32];
        acc[h] = v0 * v0 * inn[c] + v1 * v1 * inn[c + 32];
    }
#pragma unroll
    for (int h = 0; h < 16; h++) {
        float s = acc[h];
#pragma unroll
        for (int o = 16; o; o >>= 1) s += __shfl_xor_sync(0xffffffffu, s, o);
        acc[h] = s * temp[h];
    }
    float mx = acc[0];
#pragma unroll
    for (int h = 1; h < 16; h++) mx = fmaxf(mx, acc[h]);
    float ssum = 0.f;
#pragma unroll
    for (int h = 0; h < 16; h++) { acc[h] = expf(acc[h] - mx); ssum += acc[h]; }
    float inv = 1.0f / ssum;
#pragma unroll
    for (int h = 0; h < 16; h++) acc[h] *= inv;

    __shared__ float sPi[8][16];
    if (lane == 0) {
#pragma unroll
        for (int h = 0; h < 16; h++) {
            g_Pi[(size_t)r * Hh + h] = acc[h];
            sPi[warp][h] = acc[h];
        }
    }
    __syncthreads();
    if (threadIdx.x < 16) {
        float s = 0.f;
#pragma unroll
        for (int w = 0; w < 8; w++) s += sPi[w][threadIdx.x];
        g_Sp[blockIdx.x * 16 + threadIdx.x] = s;
    }
}

__global__ void reduce_S() {
    int bh = blockIdx.x;
    int b = bh >> 4, h = bh & 15;
    __shared__ float sm[128];
    float s = 0.f;
    const int blocksPerBatch = (Nseq / 8);
    for (int i = threadIdx.x; i < blocksPerBatch; i += 128)
        s += g_Sp[(b * blocksPerBatch + i) * 16 + h];
    sm[threadIdx.x] = s;
    __syncthreads();
    for (int o = 64; o; o >>= 1) {
        if (threadIdx.x < o) sm[threadIdx.x] += sm[threadIdx.x + o];
        __syncthreads();
    }
    if (threadIdx.x == 0) g_invS[bh] = 1.0f / (sm[0] + 1e-8f);
}

// ---------------- weighted column sums: sum_n Pi * w^2 ---------------------
__global__ void dots_part() {
    int c  = blockIdx.x * 256 + threadIdx.x;
    int sp = blockIdx.y;
    int b  = blockIdx.z;
    int h  = c >> 6;
    const int rows = Nseq / NSPLIT;
    const float* p   = g_w  + ((size_t)b * Nseq + (size_t)sp * rows) * DIMc + c;
    const float* pip = g_Pi + ((size_t)b * Nseq + (size_t)sp * rows) * Hh + h;
    float acc = 0.f;
    for (int i = 0; i < rows; i++) {
        float v = p[(size_t)i * DIMc];
        acc = fmaf(pip[i * Hh] * v, v, acc);
    }
    g_part2[(sp * Bb + b) * DIMc + c] = acc;
}

__global__ void reduce_attn() {
    int idx = blockIdx.x * 256 + threadIdx.x;
    int b = idx >> 10, c = idx & 1023, h = c >> 6;
    float s = 0.f;
#pragma unroll
    for (int sp = 0; sp < NSPLIT; sp++) s += g_part2[(sp * Bb + b) * DIMc + c];
    float dots = s * g_invS[b * 16 + h];
    g_attn[idx] = 1.0f / (1.0f + dots);
}

// ---------------- y = round_tf32(-w * Pi * attn) ---------------------------
__global__ void y_pass() {
    size_t i4 = (size_t)blockIdx.x * 256 + threadIdx.x;
    size_t m  = i4 >> 8;
    int cb = (int)(i4 & 255) * 4;
    int b  = (int)(m >> 12);
    float4 wv = *(const float4*)(g_w + m * DIMc + cb);
    float pi  = g_Pi[m * Hh + (cb >> 6)];
    float4 at = *(const float4*)(g_attn + (size_t)b * DIMc + cb);
    float4 r;
    r.x = to_tf32(-wv.x * pi * at.x);
    r.y = to_tf32(-wv.y * pi * at.y);
    r.z = to_tf32(-wv.z * pi * at.z);
    r.w = to_tf32(-wv.w * pi * at.w);
    *(float4*)(g_y + m * DIMc + cb) = r;
}

// ---------------- launch ---------------------------------------------------
extern "C" void kernel_launch(void* const* d_in, const int* in_sizes, int n_in,
                              void* d_out, int out_size) {
    const float* x    = (const float*)d_in[0];
    const float* Wqkv = (const float*)d_in[1];
    const float* temp = (const float*)d_in[2];
    const float* Wout = (const float*)d_in[3];
    const float* bout = (const float*)d_in[4];
    float* out = (float*)d_out;

    cudaFuncSetAttribute(gemm_mma, cudaFuncAttributeMaxDynamicSharedMemorySize, GSMEM);

    float* w_ptr;  cudaGetSymbolAddress((void**)&w_ptr,  g_w);
    float* y_ptr;  cudaGetSymbolAddress((void**)&y_ptr,  g_y);
    float* xr_ptr; cudaGetSymbolAddress((void**)&xr_ptr, g_xr);
    float* w1_ptr; cudaGetSymbolAddress((void**)&w1_ptr, g_W1r);
    float* w2_ptr; cudaGetSymbolAddress((void**)&w2_ptr, g_W2r);

    // round inputs to tf32 (RN)
    round_tf32_kernel<<<(Mm * (size_t)DIMc) / 1024, 256>>>(x, xr_ptr);
    round_tf32_kernel<<<(DIMc * DIMc) / 1024, 256>>>(Wqkv, w1_ptr);
    round_tf32_kernel<<<(DIMc * DIMc) / 1024, 256>>>(Wout, w2_ptr);

    dim3 gemmGrid(DIMc / 128, Mm / 128);               // (8, 256)
    gemm_mma<<<gemmGrid, 256, GSMEM>>>(xr_ptr, w1_ptr, w_ptr, nullptr);

    colsumsq_part<<<dim3(DIMc / 256, NSPLIT, Bb), 256>>>();
    reduce_innorm<<<(Bb * DIMc) / 256, 256>>>();
    logits_softmax<<<Mm / 8, 256>>>(temp);
    reduce_S<<<Bb * Hh, 128>>>();
    dots_part<<<dim3(DIMc / 256, NSPLIT, Bb), 256>>>();
    reduce_attn<<<(Bb * DIMc) / 256, 256>>>();
    y_pass<<<(Mm * (size_t)DIMc) / 1024, 256>>>();

    gemm_mma<<<gemmGrid, 256, GSMEM>>>(y_ptr, w2_ptr, out, bout);
}

// round 4
// speedup vs baseline: 2.8895x; 1.0040x over previous
#include <cuda_runtime.h>
#include <cstdint>

// Problem constants
#define Bb    8
#define Nseq  4096
#define DIMc  1024
#define Hh    16
#define Mm    (Bb * Nseq)      // 32768 rows
#define NSPLIT 32

// ---------------- scratch (static device allocations only) ----------------
__device__ float g_w [(size_t)Mm * DIMc];
__device__ float g_y [(size_t)Mm * DIMc];
__device__ float g_xr[(size_t)Mm * DIMc];
__device__ float g_W1r[DIMc * DIMc];
__device__ float g_W2r[DIMc * DIMc];
__device__ float g_Pi[Mm * Hh];
__device__ float g_part1[NSPLIT * Bb * DIMc];
__device__ float g_part2[NSPLIT * Bb * DIMc];
__device__ float g_innorm[Bb * DIMc];
__device__ float g_Sp[(Mm / 8) * Hh];
__device__ float g_invS[Bb * Hh];
__device__ float g_attn[Bb * DIMc];

// ============================ helpers ======================================
__device__ __forceinline__ float to_tf32(float x) {
    uint32_t u;
    asm("cvt.rna.tf32.f32 %0, %1;" : "=r"(u) : "f"(x));
    return __uint_as_float(u);
}
#define CP16(dst, src) \
    asm volatile("cp.async.cg.shared.global [%0], [%1], 16;" :: "r"(dst), "l"(src) : "memory")
#define CP_COMMIT() asm volatile("cp.async.commit_group;" ::: "memory")
#define CP_WAIT(n)  asm volatile("cp.async.wait_group %0;" :: "n"(n) : "memory")

__device__ __forceinline__ uint32_t smem_u32(const void* p) {
    uint32_t a;
    asm("{ .reg .u64 t; cvta.to.shared.u64 t, %1; cvt.u32.u64 %0, t; }"
        : "=r"(a) : "l"(p));
    return a;
}

__device__ __forceinline__ void mma_tf32(float c[4], uint32_t a0, uint32_t a1,
                                         uint32_t a2, uint32_t a3,
                                         uint32_t b0, uint32_t b1) {
    asm volatile(
        "mma.sync.aligned.m16n8k8.row.col.f32.tf32.tf32.f32 "
        "{%0,%1,%2,%3}, {%4,%5,%6,%7}, {%8,%9}, {%0,%1,%2,%3};"
        : "+f"(c[0]), "+f"(c[1]), "+f"(c[2]), "+f"(c[3])
        : "r"(a0), "r"(a1), "r"(a2), "r"(a3), "r"(b0), "r"(b1));
}

// ======================= tf32 GEMM (mma.sync) ==============================
// C[m][n] = sum_k A[m][k] * W[n][k] (+ bias[n])
// Block tile 128x128, 128 threads = 4 warps (2 M x 2 N), warp tile 64x64.
// K chunked by 16, 4-stage cp.async pipeline.
#define KC      16
#define SROW    20                        // padded smem row stride (floats)
#define STG_F   (128 * SROW * 2)          // floats per stage (A + B)
#define NSTG    4
#define GSMEM   (NSTG * STG_F * 4)        // 81920 bytes

__global__ __launch_bounds__(128)
void gemm_mma(const float* __restrict__ A, const float* __restrict__ W,
              float* __restrict__ C, const float* __restrict__ bias) {
    extern __shared__ float smem[];
    const int tid = threadIdx.x, wid = tid >> 5, lane = tid & 31;
    const int bn = blockIdx.x, bm = blockIdx.y;
    const int wm = wid & 1, wn = wid >> 1;        // 2 x 2 warp grid
    const int q  = lane >> 2, qc = lane & 3;      // fragment indices

    // cp.async assignments: 8 x 16B segments per thread per chunk
    // 1024 segs total: A = segs 0..511 (128 rows x 4), B = segs 512..1023
    const uint32_t smb = smem_u32(smem);
    uint32_t soff[8];
    const float* gptr[8];
#pragma unroll
    for (int s = 0; s < 8; s++) {
        int seg = tid + s * 128;
        int isB = seg >> 9;                        // 0: A, 1: B
        int r = (seg & 511) >> 2, cseg = seg & 3;
        soff[s] = (uint32_t)(((isB ? 128 * SROW : 0) + r * SROW + cseg * 4) * 4);
        const float* base = isB ? W + (size_t)(bn * 128 + r) * DIMc
                                : A + (size_t)(bm * 128 + r) * DIMc;
        gptr[s] = base + cseg * 4;
    }

    auto load_chunk = [&](int c) {
        uint32_t st = smb + (uint32_t)((c & 3) * STG_F) * 4;
#pragma unroll
        for (int s = 0; s < 8; s++) CP16(st + soff[s], gptr[s] + c * KC);
        CP_COMMIT();
    };

    float acc[4][8][4];
#pragma unroll
    for (int i = 0; i < 4; i++)
#pragma unroll
        for (int j = 0; j < 8; j++)
#pragma unroll
            for (int v = 0; v < 4; v++) acc[i][j][v] = 0.f;

    load_chunk(0); load_chunk(1); load_chunk(2);

    const int NCHUNK = DIMc / KC;        // 64
    for (int c = 0; c < NCHUNK; ++c) {
        CP_WAIT(2);
        __syncthreads();
        if (c + 3 < NCHUNK) load_chunk(c + 3);

        const float* As = smem + (c & 3) * STG_F;
        const float* Bs = As + 128 * SROW;
#pragma unroll
        for (int ks = 0; ks < 2; ++ks) {
            const int k0 = ks * 8;
            uint32_t af[4][4], bf[8][2];
#pragma unroll
            for (int i = 0; i < 4; i++) {
                int r0 = wm * 64 + i * 16 + q;
                af[i][0] = __float_as_uint(As[r0 * SROW + k0 + qc]);
                af[i][1] = __float_as_uint(As[(r0 + 8) * SROW + k0 + qc]);
                af[i][2] = __float_as_uint(As[r0 * SROW + k0 + qc + 4]);
                af[i][3] = __float_as_uint(As[(r0 + 8) * SROW + k0 + qc + 4]);
            }
#pragma unroll
            for (int j = 0; j < 8; j++) {
                int nr = wn * 64 + j * 8 + q;
                bf[j][0] = __float_as_uint(Bs[nr * SROW + k0 + qc]);
                bf[j][1] = __float_as_uint(Bs[nr * SROW + k0 + qc + 4]);
            }
#pragma unroll
            for (int i = 0; i < 4; i++)
#pragma unroll
                for (int j = 0; j < 8; j++)
                    mma_tf32(acc[i][j], af[i][0], af[i][1], af[i][2], af[i][3],
                             bf[j][0], bf[j][1]);
        }
        __syncthreads();
    }

    // epilogue
#pragma unroll
    for (int j = 0; j < 8; j++) {
        int col = bn * 128 + wn * 64 + j * 8 + qc * 2;
        float b0 = 0.f, b1 = 0.f;
        if (bias) { b0 = bias[col]; b1 = bias[col + 1]; }
#pragma unroll
        for (int i = 0; i < 4; i++) {
            int row = bm * 128 + wm * 64 + i * 16 + q;
            float2 v0 = make_float2(acc[i][j][0] + b0, acc[i][j][1] + b1);
            float2 v1 = make_float2(acc[i][j][2] + b0, acc[i][j][3] + b1);
            *(float2*)(C + (size_t)row * DIMc + col) = v0;
            *(float2*)(C + (size_t)(row + 8) * DIMc + col) = v1;
        }
    }
}

// =================== tf32 input rounding (RN, unbiased) ====================
__global__ void round_tf32_kernel(const float* __restrict__ src, float* __restrict__ dst) {
    size_t i = ((size_t)blockIdx.x * 256 + threadIdx.x) * 4;
    float4 v = *(const float4*)(src + i);
    v.x = to_tf32(v.x); v.y = to_tf32(v.y); v.z = to_tf32(v.z); v.w = to_tf32(v.w);
    *(float4*)(dst + i) = v;
}

// ---------------- column sums of w^2 (partial, deterministic) --------------
__global__ void colsumsq_part() {
    int c  = blockIdx.x * 256 + threadIdx.x;
    int sp = blockIdx.y;
    int b  = blockIdx.z;
    const int rows = Nseq / NSPLIT;
    const float* p = g_w + ((size_t)b * Nseq + (size_t)sp * rows) * DIMc + c;
    float acc = 0.f;
    for (int i = 0; i < rows; i++) {
        float v = p[(size_t)i * DIMc];
        acc = fmaf(v, v, acc);
    }
    g_part1[(sp * Bb + b) * DIMc + c] = acc;
}

__global__ void reduce_innorm() {
    int idx = blockIdx.x * 256 + threadIdx.x;
    int b = idx >> 10, c = idx & 1023;
    float s = 0.f;
#pragma unroll
    for (int sp = 0; sp < NSPLIT; sp++) s += g_part1[(sp * Bb + b) * DIMc + c];
    g_innorm[idx] = 1.0f / fmaxf(s, 1e-24f);
}

// ---------------- logits + softmax over heads ------------------------------
__global__ void logits_softmax(const float* __restrict__ temp) {
    int warp = threadIdx.x >> 5, lane = threadIdx.x & 31;
    int r = blockIdx.x * 8 + warp;
    int b = r >> 12;
    const float* wrow = g_w + (size_t)r * DIMc;
    const float* inn  = g_innorm + b * DIMc;

    float acc[16];
#pragma unroll
    for (int h = 0; h < 16; h++) {
        int c = h * 64 + lane;
        float v0 = wrow[c];
        float v1 = wrow[c + 32];
        acc[h] = v0 * v0 * inn[c] + v1 * v1 * inn[c + 32];
    }
#pragma unroll
    for (int h = 0; h < 16; h++) {
        float s = acc[h];
#pragma unroll
        for (int o = 16; o; o >>= 1) s += __shfl_xor_sync(0xffffffffu, s, o);
        acc[h] = s * temp[h];
    }
    float mx = acc[0];
#pragma unroll
    for (int h = 1; h < 16; h++) mx = fmaxf(mx, acc[h]);
    float ssum = 0.f;
#pragma unroll
    for (int h = 0; h < 16; h++) { acc[h] = expf(acc[h] - mx); ssum += acc[h]; }
    float inv = 1.0f / ssum;
#pragma unroll
    for (int h = 0; h < 16; h++) acc[h] *= inv;

    __shared__ float sPi[8][16];
    if (lane == 0) {
#pragma unroll
        for (int h = 0; h < 16; h++) {
            g_Pi[(size_t)r * Hh + h] = acc[h];
            sPi[warp][h] = acc[h];
        }
    }
    __syncthreads();
    if (threadIdx.x < 16) {
        float s = 0.f;
#pragma unroll
        for (int w = 0; w < 8; w++) s += sPi[w][threadIdx.x];
        g_Sp[blockIdx.x * 16 + threadIdx.x] = s;
    }
}

__global__ void reduce_S() {
    int bh = blockIdx.x;
    int b = bh >> 4, h = bh & 15;
    __shared__ float sm[128];
    float s = 0.f;
    const int blocksPerBatch = (Nseq / 8);
    for (int i = threadIdx.x; i < blocksPerBatch; i += 128)
        s += g_Sp[(b * blocksPerBatch + i) * 16 + h];
    sm[threadIdx.x] = s;
    __syncthreads();
    for (int o = 64; o; o >>= 1) {
        if (threadIdx.x < o) sm[threadIdx.x] += sm[threadIdx.x + o];
        __syncthreads();
    }
    if (threadIdx.x == 0) g_invS[bh] = 1.0f / (sm[0] + 1e-8f);
}

// ---------------- weighted column sums: sum_n Pi * w^2 ---------------------
__global__ void dots_part() {
    int c  = blockIdx.x * 256 + threadIdx.x;
    int sp = blockIdx.y;
    int b  = blockIdx.z;
    int h  = c >> 6;
    const int rows = Nseq / NSPLIT;
    const float* p   = g_w  + ((size_t)b * Nseq + (size_t)sp * rows) * DIMc + c;
    const float* pip = g_Pi + ((size_t)b * Nseq + (size_t)sp * rows) * Hh + h;
    float acc = 0.f;
    for (int i = 0; i < rows; i++) {
        float v = p[(size_t)i * DIMc];
        acc = fmaf(pip[i * Hh] * v, v, acc);
    }
    g_part2[(sp * Bb + b) * DIMc + c] = acc;
}

__global__ void reduce_attn() {
    int idx = blockIdx.x * 256 + threadIdx.x;
    int b = idx >> 10, c = idx & 1023, h = c >> 6;
    float s = 0.f;
#pragma unroll
    for (int sp = 0; sp < NSPLIT; sp++) s += g_part2[(sp * Bb + b) * DIMc + c];
    float dots = s * g_invS[b * 16 + h];
    g_attn[idx] = 1.0f / (1.0f + dots);
}

// ---------------- y = round_tf32(-w * Pi * attn) ---------------------------
__global__ void y_pass() {
    size_t i4 = (size_t)blockIdx.x * 256 + threadIdx.x;
    size_t m  = i4 >> 8;
    int cb = (int)(i4 & 255) * 4;
    int b  = (int)(m >> 12);
    float4 wv = *(const float4*)(g_w + m * DIMc + cb);
    float pi  = g_Pi[m * Hh + (cb >> 6)];
    float4 at = *(const float4*)(g_attn + (size_t)b * DIMc + cb);
    float4 r;
    r.x = to_tf32(-wv.x * pi * at.x);
    r.y = to_tf32(-wv.y * pi * at.y);
    r.z = to_tf32(-wv.z * pi * at.z);
    r.w = to_tf32(-wv.w * pi * at.w);
    *(float4*)(g_y + m * DIMc + cb) = r;
}

// ---------------- launch ---------------------------------------------------
extern "C" void kernel_launch(void* const* d_in, const int* in_sizes, int n_in,
                              void* d_out, int out_size) {
    const float* x    = (const float*)d_in[0];
    const float* Wqkv = (const float*)d_in[1];
    const float* temp = (const float*)d_in[2];
    const float* Wout = (const float*)d_in[3];
    const float* bout = (const float*)d_in[4];
    float* out = (float*)d_out;

    cudaFuncSetAttribute(gemm_mma, cudaFuncAttributeMaxDynamicSharedMemorySize, GSMEM);

    float* w_ptr;  cudaGetSymbolAddress((void**)&w_ptr,  g_w);
    float* y_ptr;  cudaGetSymbolAddress((void**)&y_ptr,  g_y);
    float* xr_ptr; cudaGetSymbolAddress((void**)&xr_ptr, g_xr);
    float* w1_ptr; cudaGetSymbolAddress((void**)&w1_ptr, g_W1r);
    float* w2_ptr; cudaGetSymbolAddress((void**)&w2_ptr, g_W2r);

    round_tf32_kernel<<<(Mm * (size_t)DIMc) / 1024, 256>>>(x, xr_ptr);
    round_tf32_kernel<<<(DIMc * DIMc) / 1024, 256>>>(Wqkv, w1_ptr);
    round_tf32_kernel<<<(DIMc * DIMc) / 1024, 256>>>(Wout, w2_ptr);

    dim3 gemmGrid(DIMc / 128, Mm / 128);               // (8, 256)
    gemm_mma<<<gemmGrid, 128, GSMEM>>>(xr_ptr, w1_ptr, w_ptr, nullptr);

    colsumsq_part<<<dim3(DIMc / 256, NSPLIT, Bb), 256>>>();
    reduce_innorm<<<(Bb * DIMc) / 256, 256>>>();
    logits_softmax<<<Mm / 8, 256>>>(temp);
    reduce_S<<<Bb * Hh, 128>>>();
    dots_part<<<dim3(DIMc / 256, NSPLIT, Bb), 256>>>();
    reduce_attn<<<(Bb * DIMc) / 256, 256>>>();
    y_pass<<<(Mm * (size_t)DIMc) / 1024, 256>>>();

    gemm_mma<<<gemmGrid, 128, GSMEM>>>(y_ptr, w2_ptr, out, bout);
}

// round 5
// speedup vs baseline: 6.2586x; 2.1660x over previous
#include <cuda_runtime.h>
#include <cuda_fp16.h>
#include <cstdint>

// Problem constants
#define Bb    8
#define Nseq  4096
#define DIMc  1024
#define Hh    16
#define Mm    (Bb * Nseq)      // 32768 rows
#define NSPLIT 32

// ---------------- scratch (static device allocations only) ----------------
__device__ float  g_w [(size_t)Mm * DIMc];          // fp32 qkv output
__device__ __align__(16) __half g_xh[(size_t)Mm * DIMc];   // x in fp16
__device__ __align__(16) __half g_yh[(size_t)Mm * DIMc];   // y in fp16
__device__ __align__(16) __half g_W1h[DIMc * DIMc];
__device__ __align__(16) __half g_W2h[DIMc * DIMc];
__device__ float g_Pi[Mm * Hh];
__device__ float g_part1[NSPLIT * Bb * DIMc];
__device__ float g_part2[NSPLIT * Bb * DIMc];
__device__ float g_innorm[Bb * DIMc];
__device__ float g_Sp[(Mm / 8) * Hh];
__device__ float g_invS[Bb * Hh];
__device__ float g_attn[Bb * DIMc];

// ============================ helpers ======================================
#define CP16(dst, src) \
    asm volatile("cp.async.cg.shared.global [%0], [%1], 16;" :: "r"(dst), "l"(src) : "memory")
#define CP_COMMIT() asm volatile("cp.async.commit_group;" ::: "memory")
#define CP_WAIT(n)  asm volatile("cp.async.wait_group %0;" :: "n"(n) : "memory")

__device__ __forceinline__ uint32_t smem_u32(const void* p) {
    uint32_t a;
    asm("{ .reg .u64 t; cvta.to.shared.u64 t, %1; cvt.u32.u64 %0, t; }"
        : "=r"(a) : "l"(p));
    return a;
}
#define LDSM4(r0, r1, r2, r3, addr) \
    asm volatile("ldmatrix.sync.aligned.m8n8.x4.shared.b16 {%0,%1,%2,%3}, [%4];" \
        : "=r"(r0), "=r"(r1), "=r"(r2), "=r"(r3) : "r"(addr))

__device__ __forceinline__ void mma_f16(float c[4], uint32_t a0, uint32_t a1,
                                        uint32_t a2, uint32_t a3,
                                        uint32_t b0, uint32_t b1) {
    asm volatile(
        "mma.sync.aligned.m16n8k16.row.col.f32.f16.f16.f32 "
        "{%0,%1,%2,%3}, {%4,%5,%6,%7}, {%8,%9}, {%0,%1,%2,%3};"
        : "+f"(c[0]), "+f"(c[1]), "+f"(c[2]), "+f"(c[3])
        : "r"(a0), "r"(a1), "r"(a2), "r"(a3), "r"(b0), "r"(b1));
}

// ======================= fp16 GEMM (mma.sync m16n8k16) =====================
// C[m][n] = sum_k A[m][k] * W[n][k] (+ bias[n]),  A/W fp16, C fp32
// Block tile 128x128, 128 threads = 4 warps (2M x 2N), warp tile 64x64.
// K chunked by 32 (2 ks of k16), 4-stage cp.async pipeline, ldmatrix frags.
#define KC      32
#define SROWH   40                          // padded smem row stride (halfs)
#define STG_B   (128 * SROWH * 2 * 2)       // bytes per stage (A + B) = 20480
#define NSTG    4
#define GSMEM   (NSTG * STG_B)              // 81920 bytes

__global__ __launch_bounds__(128)
void gemm_f16(const __half* __restrict__ A, const __half* __restrict__ W,
              float* __restrict__ C, const float* __restrict__ bias) {
    extern __shared__ __half smemh[];
    const int tid = threadIdx.x, wid = tid >> 5, lane = tid & 31;
    const int bn = blockIdx.x, bm = blockIdx.y;
    const int wm = wid & 1, wn = wid >> 1;        // 2 x 2 warp grid
    const int q  = lane >> 2, qc = lane & 3;      // C-fragment indices
    const uint32_t smb = smem_u32(smemh);

    // ---- cp.async assignments: 8 x 16B segments per thread per chunk ----
    // 1024 segs: A = segs 0..511 (128 rows x 4 of 8 halfs), B = 512..1023
    uint32_t soff[8];
    const __half* gptr[8];
#pragma unroll
    for (int s = 0; s < 8; s++) {
        int seg = tid + s * 128;
        int isB = seg >> 9;
        int r = (seg & 511) >> 2, cseg = seg & 3;
        soff[s] = (uint32_t)(isB * (128 * SROWH * 2) + (r * SROWH + cseg * 8) * 2);
        const __half* base = isB ? W + (size_t)(bn * 128 + r) * DIMc
                                 : A + (size_t)(bm * 128 + r) * DIMc;
        gptr[s] = base + cseg * 8;
    }
    auto load_chunk = [&](int c) {
        uint32_t st = smb + (uint32_t)((c & 3) * STG_B);
#pragma unroll
        for (int s = 0; s < 8; s++) CP16(st + soff[s], gptr[s] + c * KC);
        CP_COMMIT();
    };

    // ---- ldmatrix address components (byte offsets within stage) ----
    // A x4 for tile (i,ks): matrices {m0-7/k0-7, m8-15/k0-7, m0-7/k8-15, m8-15/k8-15}
    const int arow = (lane & 7) + 8 * ((lane >> 3) & 1);
    const int acol = 8 * (lane >> 4);
    // B x4 for j-pair jp: matrices {n0-7/k0-7, n0-7/k8-15, n8-15/k0-7, n8-15/k8-15}
    const int brow = (lane & 7) + 8 * (lane >> 4);
    const int bcol = 8 * ((lane >> 3) & 1);

    float acc[4][8][4];
#pragma unroll
    for (int i = 0; i < 4; i++)
#pragma unroll
        for (int j = 0; j < 8; j++)
#pragma unroll
            for (int v = 0; v < 4; v++) acc[i][j][v] = 0.f;

    load_chunk(0); load_chunk(1); load_chunk(2);

    const int NCHUNK = DIMc / KC;        // 32
    for (int c = 0; c < NCHUNK; ++c) {
        CP_WAIT(2);
        __syncthreads();
        if (c + 3 < NCHUNK) load_chunk(c + 3);

        uint32_t stA = smb + (uint32_t)((c & 3) * STG_B);
        uint32_t stB = stA + 128 * SROWH * 2;
#pragma unroll
        for (int ks = 0; ks < 2; ++ks) {
            const int k0 = ks * 16;
            uint32_t af[4][4], bf[8][2];
#pragma unroll
            for (int i = 0; i < 4; i++) {
                uint32_t ad = stA + (uint32_t)(((wm * 64 + i * 16 + arow) * SROWH
                                                + k0 + acol) * 2);
                LDSM4(af[i][0], af[i][1], af[i][2], af[i][3], ad);
            }
#pragma unroll
            for (int jp = 0; jp < 4; jp++) {
                uint32_t bd = stB + (uint32_t)(((wn * 64 + jp * 16 + brow) * SROWH
                                                + k0 + bcol) * 2);
                uint32_t r0, r1, r2, r3;
                LDSM4(r0, r1, r2, r3, bd);
                bf[jp * 2][0] = r0; bf[jp * 2][1] = r1;
                bf[jp * 2 + 1][0] = r2; bf[jp * 2 + 1][1] = r3;
            }
#pragma unroll
            for (int i = 0; i < 4; i++)
#pragma unroll
                for (int j = 0; j < 8; j++)
                    mma_f16(acc[i][j], af[i][0], af[i][1], af[i][2], af[i][3],
                            bf[j][0], bf[j][1]);
        }
        __syncthreads();
    }

    // epilogue (fp32 out)
#pragma unroll
    for (int j = 0; j < 8; j++) {
        int col = bn * 128 + wn * 64 + j * 8 + qc * 2;
        float b0 = 0.f, b1 = 0.f;
        if (bias) { b0 = bias[col]; b1 = bias[col + 1]; }
#pragma unroll
        for (int i = 0; i < 4; i++) {
            int row = bm * 128 + wm * 64 + i * 16 + q;
            float2 v0 = make_float2(acc[i][j][0] + b0, acc[i][j][1] + b1);
            float2 v1 = make_float2(acc[i][j][2] + b0, acc[i][j][3] + b1);
            *(float2*)(C + (size_t)row * DIMc + col) = v0;
            *(float2*)(C + (size_t)(row + 8) * DIMc + col) = v1;
        }
    }
}

// =================== fp32 -> fp16 conversion ===============================
__global__ void f32_to_f16(const float* __restrict__ src, __half* __restrict__ dst) {
    size_t i = ((size_t)blockIdx.x * 256 + threadIdx.x) * 8;
    float4 v0 = *(const float4*)(src + i);
    float4 v1 = *(const float4*)(src + i + 4);
    __half2 h[4];
    h[0] = __floats2half2_rn(v0.x, v0.y);
    h[1] = __floats2half2_rn(v0.z, v0.w);
    h[2] = __floats2half2_rn(v1.x, v1.y);
    h[3] = __floats2half2_rn(v1.z, v1.w);
    *(uint4*)(dst + i) = *(uint4*)h;
}

// ---------------- column sums of w^2 (partial, deterministic) --------------
__global__ void colsumsq_part() {
    int c  = blockIdx.x * 256 + threadIdx.x;
    int sp = blockIdx.y;
    int b  = blockIdx.z;
    const int rows = Nseq / NSPLIT;
    const float* p = g_w + ((size_t)b * Nseq + (size_t)sp * rows) * DIMc + c;
    float acc = 0.f;
    for (int i = 0; i < rows; i++) {
        float v = p[(size_t)i * DIMc];
        acc = fmaf(v, v, acc);
    }
    g_part1[(sp * Bb + b) * DIMc + c] = acc;
}

__global__ void reduce_innorm() {
    int idx = blockIdx.x * 256 + threadIdx.x;
    int b = idx >> 10, c = idx & 1023;
    float s = 0.f;
#pragma unroll
    for (int sp = 0; sp < NSPLIT; sp++) s += g_part1[(sp * Bb + b) * DIMc + c];
    g_innorm[idx] = 1.0f / fmaxf(s, 1e-24f);
}

// ---------------- logits + softmax over heads ------------------------------
__global__ void logits_softmax(const float* __restrict__ temp) {
    int warp = threadIdx.x >> 5, lane = threadIdx.x & 31;
    int r = blockIdx.x * 8 + warp;
    int b = r >> 12;
    const float* wrow = g_w + (size_t)r * DIMc;
    const float* inn  = g_innorm + b * DIMc;

    float acc[16];
#pragma unroll
    for (int h = 0; h < 16; h++) {
        int c = h * 64 + lane;
        float v0 = wrow[c];
        float v1 = wrow[c + 32];
        acc[h] = v0 * v0 * inn[c] + v1 * v1 * inn[c + 32];
    }
#pragma unroll
    for (int h = 0; h < 16; h++) {
        float s = acc[h];
#pragma unroll
        for (int o = 16; o; o >>= 1) s += __shfl_xor_sync(0xffffffffu, s, o);
        acc[h] = s * temp[h];
    }
    float mx = acc[0];
#pragma unroll
    for (int h = 1; h < 16; h++) mx = fmaxf(mx, acc[h]);
    float ssum = 0.f;
#pragma unroll
    for (int h = 0; h < 16; h++) { acc[h] = expf(acc[h] - mx); ssum += acc[h]; }
    float inv = 1.0f / ssum;
#pragma unroll
    for (int h = 0; h < 16; h++) acc[h] *= inv;

    __shared__ float sPi[8][16];
    if (lane == 0) {
#pragma unroll
        for (int h = 0; h < 16; h++) {
            g_Pi[(size_t)r * Hh + h] = acc[h];
            sPi[warp][h] = acc[h];
        }
    }
    __syncthreads();
    if (threadIdx.x < 16) {
        float s = 0.f;
#pragma unroll
        for (int w = 0; w < 8; w++) s += sPi[w][threadIdx.x];
        g_Sp[blockIdx.x * 16 + threadIdx.x] = s;
    }
}

__global__ void reduce_S() {
    int bh = blockIdx.x;
    int b = bh >> 4, h = bh & 15;
    __shared__ float sm[128];
    float s = 0.f;
    const int blocksPerBatch = (Nseq / 8);
    for (int i = threadIdx.x; i < blocksPerBatch; i += 128)
        s += g_Sp[(b * blocksPerBatch + i) * 16 + h];
    sm[threadIdx.x] = s;
    __syncthreads();
    for (int o = 64; o; o >>= 1) {
        if (threadIdx.x < o) sm[threadIdx.x] += sm[threadIdx.x + o];
        __syncthreads();
    }
    if (threadIdx.x == 0) g_invS[bh] = 1.0f / (sm[0] + 1e-8f);
}

// ---------------- weighted column sums: sum_n Pi * w^2 ---------------------
__global__ void dots_part() {
    int c  = blockIdx.x * 256 + threadIdx.x;
    int sp = blockIdx.y;
    int b  = blockIdx.z;
    int h  = c >> 6;
    const int rows = Nseq / NSPLIT;
    const float* p   = g_w  + ((size_t)b * Nseq + (size_t)sp * rows) * DIMc + c;
    const float* pip = g_Pi + ((size_t)b * Nseq + (size_t)sp * rows) * Hh + h;
    float acc = 0.f;
    for (int i = 0; i < rows; i++) {
        float v = p[(size_t)i * DIMc];
        acc = fmaf(pip[i * Hh] * v, v, acc);
    }
    g_part2[(sp * Bb + b) * DIMc + c] = acc;
}

__global__ void reduce_attn() {
    int idx = blockIdx.x * 256 + threadIdx.x;
    int b = idx >> 10, c = idx & 1023, h = c >> 6;
    float s = 0.f;
#pragma unroll
    for (int sp = 0; sp < NSPLIT; sp++) s += g_part2[(sp * Bb + b) * DIMc + c];
    float dots = s * g_invS[b * 16 + h];
    g_attn[idx] = 1.0f / (1.0f + dots);
}

// ---------------- y = fp16(-w * Pi * attn) ---------------------------------
__global__ void y_pass() {
    size_t i4 = (size_t)blockIdx.x * 256 + threadIdx.x;
    size_t m  = i4 >> 8;
    int cb = (int)(i4 & 255) * 4;
    int b  = (int)(m >> 12);
    float4 wv = *(const float4*)(g_w + m * DIMc + cb);
    float pi  = g_Pi[m * Hh + (cb >> 6)];
    float4 at = *(const float4*)(g_attn + (size_t)b * DIMc + cb);
    __half2 h0 = __floats2half2_rn(-wv.x * pi * at.x, -wv.y * pi * at.y);
    __half2 h1 = __floats2half2_rn(-wv.z * pi * at.z, -wv.w * pi * at.w);
    uint2 pk = make_uint2(*(uint32_t*)&h0, *(uint32_t*)&h1);
    *(uint2*)(g_yh + m * DIMc + cb) = pk;
}

// ---------------- launch ---------------------------------------------------
extern "C" void kernel_launch(void* const* d_in, const int* in_sizes, int n_in,
                              void* d_out, int out_size) {
    const float* x    = (const float*)d_in[0];
    const float* Wqkv = (const float*)d_in[1];
    const float* temp = (const float*)d_in[2];
    const float* Wout = (const float*)d_in[3];
    const float* bout = (const float*)d_in[4];
    float* out = (float*)d_out;

    cudaFuncSetAttribute(gemm_f16, cudaFuncAttributeMaxDynamicSharedMemorySize, GSMEM);

    float*  w_ptr;  cudaGetSymbolAddress((void**)&w_ptr,  g_w);
    __half* xh_ptr; cudaGetSymbolAddress((void**)&xh_ptr, g_xh);
    __half* yh_ptr; cudaGetSymbolAddress((void**)&yh_ptr, g_yh);
    __half* w1_ptr; cudaGetSymbolAddress((void**)&w1_ptr, g_W1h);
    __half* w2_ptr; cudaGetSymbolAddress((void**)&w2_ptr, g_W2h);

    f32_to_f16<<<(Mm * (size_t)DIMc) / 2048, 256>>>(x, xh_ptr);
    f32_to_f16<<<(DIMc * DIMc) / 2048, 256>>>(Wqkv, w1_ptr);
    f32_to_f16<<<(DIMc * DIMc) / 2048, 256>>>(Wout, w2_ptr);

    dim3 gemmGrid(DIMc / 128, Mm / 128);               // (8, 256)
    gemm_f16<<<gemmGrid, 128, GSMEM>>>(xh_ptr, w1_ptr, w_ptr, nullptr);

    colsumsq_part<<<dim3(DIMc / 256, NSPLIT, Bb), 256>>>();
    reduce_innorm<<<(Bb * DIMc) / 256, 256>>>();
    logits_softmax<<<Mm / 8, 256>>>(temp);
    reduce_S<<<Bb * Hh, 128>>>();
    dots_part<<<dim3(DIMc / 256, NSPLIT, Bb), 256>>>();
    reduce_attn<<<(Bb * DIMc) / 256, 256>>>();
    y_pass<<<(Mm * (size_t)DIMc) / 1024, 256>>>();

    gemm_f16<<<gemmGrid, 128, GSMEM>>>(yh_ptr, w2_ptr, out, bout);
}